// round 13
// baseline (speedup 1.0000x reference)
#include <cuda_runtime.h>
#include <cuda_fp16.h>
#include <math.h>

#define NN   50000
#define EE   800000
#define GGR  16
#define DD   64
#define LLY  4
#define INF  7
#define ETOT (EE + NN)
#define NEGS 0.2f
#define LN_EPS 1e-5f
#define DEG_BLOCKS 1024
#define SCAN_BLOCKS ((NN + 1023) / 1024)

// ---------------- device scratch ----------------
__device__ __align__(16) float  g_h[NN * DD];
__device__ __align__(16) __half g_xlh[NN * 256];
__device__ __align__(16) __half g_xrh[NN * 256];
__device__ int    g_deg[NN];
__device__ int    g_rowptr[NN + 1];
__device__ int    g_fillptr[NN];
__device__ int    g_bsum[SCAN_BLOCKS];
__device__ int    g_boff[SCAN_BLOCKS];
__device__ __align__(16) float4 g_sea[ETOT];   // {src(asfloat), ea0, ea1, ea2}
__device__ float  g_eapart[DEG_BLOCKS * 3];
__device__ float  g_easum[3];
__device__ int    g_cnt[GGR];
__device__ float  g_gmean[GGR * DD];
__device__ float  g_gmax[GGR * DD];
__device__ float  g_gate[GGR * DD];

__device__ __forceinline__ float lrelu(float x) {
    return fmaxf(x, 0.f) + NEGS * fminf(x, 0.f);
}

__device__ __forceinline__ void atomicMaxFloat(float* addr, float v) {
    if (v >= 0.f) atomicMax((int*)addr, __float_as_int(v));
    else          atomicMin((unsigned int*)addr, __float_as_uint(v));
}
__device__ __forceinline__ void atomicMaxFloatS(float* addr, float v) {
    if (v >= 0.f) atomicMax((int*)addr, __float_as_int(v));
    else          atomicMin((unsigned int*)addr, __float_as_uint(v));
}

// ---------------- setup ----------------
__global__ void k_zero() {
    int i = blockIdx.x * blockDim.x + threadIdx.x;
    if (i < NN)  g_deg[i] = 1;          // self loop pre-counted
    if (i < GGR) g_cnt[i] = 0;
    if (i < GGR * DD) { g_gmean[i] = 0.f; g_gmax[i] = -3.402823466e38f; }
}

__global__ void k_deg(const int* __restrict__ ei, const float* __restrict__ ea) {
    __shared__ float p0s[8], p1s[8], p2s[8];
    float s0 = 0.f, s1 = 0.f, s2 = 0.f;
    int stride = gridDim.x * blockDim.x;
    for (int e = blockIdx.x * blockDim.x + threadIdx.x; e < EE; e += stride) {
        atomicAdd(&g_deg[ei[EE + e]], 1);
        s0 += ea[e * 3 + 0];
        s1 += ea[e * 3 + 1];
        s2 += ea[e * 3 + 2];
    }
    #pragma unroll
    for (int off = 16; off; off >>= 1) {
        s0 += __shfl_down_sync(0xffffffffu, s0, off);
        s1 += __shfl_down_sync(0xffffffffu, s1, off);
        s2 += __shfl_down_sync(0xffffffffu, s2, off);
    }
    int w = threadIdx.x >> 5;
    if ((threadIdx.x & 31) == 0) { p0s[w] = s0; p1s[w] = s1; p2s[w] = s2; }
    __syncthreads();
    if (threadIdx.x == 0) {
        float a = 0.f, b = 0.f, c = 0.f;
        #pragma unroll
        for (int i = 0; i < 8; i++) { a += p0s[i]; b += p1s[i]; c += p2s[i]; }
        g_eapart[blockIdx.x * 3 + 0] = a;
        g_eapart[blockIdx.x * 3 + 1] = b;
        g_eapart[blockIdx.x * 3 + 2] = c;
    }
}

// ---- 3-phase parallel exclusive scan of g_deg ----
__global__ void k_scan1() {            // grid SCAN_BLOCKS, block 1024
    __shared__ int wsum[32];
    int t = threadIdx.x, lane = t & 31, w = t >> 5;
    int i = blockIdx.x * 1024 + t;
    int v = (i < NN) ? g_deg[i] : 0;
    int incl = v;
    #pragma unroll
    for (int off = 1; off < 32; off <<= 1) {
        int u = __shfl_up_sync(0xffffffffu, incl, off);
        if (lane >= off) incl += u;
    }
    if (lane == 31) wsum[w] = incl;
    __syncthreads();
    if (w == 0) {
        int x = wsum[lane];
        int xin = x;
        #pragma unroll
        for (int off = 1; off < 32; off <<= 1) {
            int u = __shfl_up_sync(0xffffffffu, xin, off);
            if (lane >= off) xin += u;
        }
        wsum[lane] = xin - x;
    }
    __syncthreads();
    int excl = wsum[w] + incl - v;
    if (i < NN) g_rowptr[i] = excl;        // block-local exclusive
    if (t == 1023) g_bsum[blockIdx.x] = wsum[31] + incl;
}

__global__ void k_scan2() {            // 1 block, 128 threads
    int t = threadIdx.x, lane = t & 31, w = t >> 5;
    if (w < 3) {
        float s = 0.f;
        for (int i = lane; i < DEG_BLOCKS; i += 32) s += g_eapart[i * 3 + w];
        #pragma unroll
        for (int off = 16; off; off >>= 1)
            s += __shfl_down_sync(0xffffffffu, s, off);
        if (lane == 0) g_easum[w] = s;
    }
    if (w == 3 && lane == 0) {
        int run = 0;
        for (int b = 0; b < SCAN_BLOCKS; b++) { g_boff[b] = run; run += g_bsum[b]; }
        g_rowptr[NN] = run;
    }
}

__global__ void k_scan3() {            // grid SCAN_BLOCKS, block 1024
    int i = blockIdx.x * 1024 + threadIdx.x;
    if (i < NN) {
        int val = g_rowptr[i] + g_boff[blockIdx.x];
        g_rowptr[i]  = val;
        g_fillptr[i] = val;
    }
}

__global__ void k_fill(const int* __restrict__ ei, const float* __restrict__ ea,
                       const int* __restrict__ batch) {
    const float inv_e = 1.f / (float)EE;
    float em0 = g_easum[0] * inv_e, em1 = g_easum[1] * inv_e, em2 = g_easum[2] * inv_e;
    int stride = gridDim.x * blockDim.x;
    for (int e = blockIdx.x * blockDim.x + threadIdx.x; e < ETOT; e += stride) {
        int dst; float4 v;
        if (e < EE) {
            dst = ei[EE + e];
            v = make_float4(__int_as_float(ei[e]), ea[e*3], ea[e*3+1], ea[e*3+2]);
        } else {
            dst = e - EE;
            v = make_float4(__int_as_float(dst), em0, em1, em2);
            atomicAdd(&g_cnt[batch[e - EE]], 1);
        }
        int pos = atomicAdd(&g_fillptr[dst], 1);
        g_sea[pos] = v;
    }
}

// ---------------- encoder ----------------
__global__ void k_enc(const float* __restrict__ x, const float* __restrict__ W,
                      const float* __restrict__ b) {
    __shared__ float Ws[INF * DD];
    __shared__ float bs[DD];
    int t = threadIdx.x;
    for (int i = t; i < INF * DD; i += blockDim.x) Ws[i] = W[i];
    for (int i = t; i < DD; i += blockDim.x) bs[i] = b[i];
    __syncthreads();
    int lane = t & 31, w = t >> 5;
    int n = blockIdx.x * 8 + w;
    if (n >= NN) return;
    float xv[INF];
    #pragma unroll
    for (int k = 0; k < INF; k++) xv[k] = x[n * INF + k];
    #pragma unroll
    for (int i = 0; i < 2; i++) {
        int d = lane + 32 * i;
        float acc = bs[d];
        #pragma unroll
        for (int k = 0; k < INF; k++) acc = fmaf(xv[k], Ws[k * DD + d], acc);
        g_h[n * DD + d] = acc;
    }
}

// ---------------- xl/xr GEMM (fp32 FMA, fp16 store); applies prev-layer gate ----------------
__global__ void __launch_bounds__(256, 2)
k_xlxr(const float* __restrict__ Wl, const float* __restrict__ bl,
       const float* __restrict__ Wr, const float* __restrict__ br,
       const int* __restrict__ batch, int use_gate) {
    __shared__ float hsh[32 * 64];
    int t = threadIdx.x;
    int n0 = blockIdx.x * 32;
    for (int i = t; i < 32 * 64; i += 256) {
        int nn = n0 + (i >> 6);
        int d = i & 63;
        float v = 0.f;
        if (nn < NN) {
            v = g_h[nn * 64 + d];
            if (use_gate) {
                v *= g_gate[batch[nn] * 64 + d];
                g_h[nn * 64 + d] = v;
            }
        }
        hsh[i] = v;
    }
    __syncthreads();
    int cg = t & 63, rg = t >> 6;
    int j0 = cg * 8;
    const float* W  = (j0 < 256) ? Wl : Wr;
    const float* bb = (j0 < 256) ? bl : br;
    __half* out = (j0 < 256) ? g_xlh : g_xrh;
    int jj = (j0 < 256) ? j0 : (j0 - 256);

    float acc[8][8];
    #pragma unroll
    for (int r = 0; r < 8; r++)
        #pragma unroll
        for (int c = 0; c < 8; c++) acc[r][c] = 0.f;

    #pragma unroll 4
    for (int k = 0; k < 64; k++) {
        float4 w0 = *(const float4*)(W + k * 256 + jj);
        float4 w1 = *(const float4*)(W + k * 256 + jj + 4);
        float wv[8] = {w0.x, w0.y, w0.z, w0.w, w1.x, w1.y, w1.z, w1.w};
        #pragma unroll
        for (int r = 0; r < 8; r++) {
            float hv = hsh[(rg * 8 + r) * 64 + k];
            #pragma unroll
            for (int c = 0; c < 8; c++) acc[r][c] = fmaf(hv, wv[c], acc[r][c]);
        }
    }
    float bv[8];
    #pragma unroll
    for (int c = 0; c < 8; c++) bv[c] = bb[jj + c];
    #pragma unroll
    for (int r = 0; r < 8; r++) {
        int n = n0 + rg * 8 + r;
        if (n < NN) {
            __half2 p0 = __floats2half2_rn(acc[r][0]+bv[0], acc[r][1]+bv[1]);
            __half2 p1 = __floats2half2_rn(acc[r][2]+bv[2], acc[r][3]+bv[3]);
            __half2 p2 = __floats2half2_rn(acc[r][4]+bv[4], acc[r][5]+bv[5]);
            __half2 p3 = __floats2half2_rn(acc[r][6]+bv[6], acc[r][7]+bv[7]);
            uint4 u = make_uint4(*(unsigned*)&p0, *(unsigned*)&p1,
                                 *(unsigned*)&p2, *(unsigned*)&p3);
            *(uint4*)(out + (size_t)n * 256 + jj) = u;
        }
    }
}

// ---------------- fused GATv2: half2 score math, fp32 softmax/accum, LN1 ----------------
__global__ void __launch_bounds__(256, 4)
k_gat(const float* __restrict__ We, const float* __restrict__ attw,
      const float* __restrict__ gatb, const float* __restrict__ lnw,
      const float* __restrict__ lnb) {
    int t = threadIdx.x, lane = t & 31, w = t >> 5;
    int n = blockIdx.x * 8 + w;
    if (n >= NN) return;
    int v0 = lane * 8;

    // loop-invariant constants packed as half2 (20 regs instead of 40)
    __half2 we0h[4], we1h[4], we2h[4], avh[4], xrh[4];
    #pragma unroll
    for (int q = 0; q < 4; q++) {
        we0h[q] = __floats2half2_rn(We[v0 + 2*q],       We[v0 + 2*q + 1]);
        we1h[q] = __floats2half2_rn(We[256 + v0 + 2*q], We[256 + v0 + 2*q + 1]);
        we2h[q] = __floats2half2_rn(We[512 + v0 + 2*q], We[512 + v0 + 2*q + 1]);
        avh[q]  = __floats2half2_rn(attw[v0 + 2*q],     attw[v0 + 2*q + 1]);
    }
    {
        uint4 xp = *(const uint4*)(g_xrh + (size_t)n * 256 + v0);
        *(unsigned*)&xrh[0] = xp.x; *(unsigned*)&xrh[1] = xp.y;
        *(unsigned*)&xrh[2] = xp.z; *(unsigned*)&xrh[3] = xp.w;
    }
    const __half2 z2   = __float2half2_rn(0.f);
    const __half2 neg2 = __float2half2_rn(NEGS);

    int beg = g_rowptr[n], end = g_rowptr[n + 1];

    float m = -INFINITY, den = 0.f;
    float acc[8] = {0.f,0.f,0.f,0.f,0.f,0.f,0.f,0.f};

    float4 se0 = make_float4(0.f,0.f,0.f,0.f), se1 = se0;
    uint4 xl0 = make_uint4(0,0,0,0);
    if (beg < end)     se0 = g_sea[beg];
    if (beg + 1 < end) se1 = g_sea[beg + 1];
    if (beg < end)
        xl0 = *(const uint4*)(g_xlh + (size_t)__float_as_int(se0.x) * 256 + v0);

    for (int k = beg; k < end; k++) {
        uint4 xl1 = xl0;
        if (k + 1 < end)
            xl1 = *(const uint4*)(g_xlh + (size_t)__float_as_int(se1.x) * 256 + v0);
        float4 se2 = (k + 2 < end) ? g_sea[k + 2] : se1;

        __half2 xlh[4];
        *(unsigned*)&xlh[0] = xl0.x; *(unsigned*)&xlh[1] = xl0.y;
        *(unsigned*)&xlh[2] = xl0.z; *(unsigned*)&xlh[3] = xl0.w;

        __half2 ea0 = __float2half2_rn(se0.y);
        __half2 ea1 = __float2half2_rn(se0.z);
        __half2 ea2 = __float2half2_rn(se0.w);

        // score math in half2 (xl/xr are fp16 already)
        __half2 pacc = z2;
        #pragma unroll
        for (int q = 0; q < 4; q++) {
            __half2 sv = __hadd2(xlh[q], xrh[q]);
            sv = __hfma2(ea0, we0h[q], sv);
            sv = __hfma2(ea1, we1h[q], sv);
            sv = __hfma2(ea2, we2h[q], sv);
            __half2 lr = __hfma2(neg2, __hmin2(sv, z2), __hmax2(sv, z2));
            pacc = __hfma2(avh[q], lr, pacc);
        }
        float2 pf = __half22float2(pacc);
        float p = pf.x + pf.y;
        p += __shfl_xor_sync(0xffffffffu, p, 1);
        p += __shfl_xor_sync(0xffffffffu, p, 2);
        p += __shfl_xor_sync(0xffffffffu, p, 4);
        float mo = m;
        m = fmaxf(m, p);
        float c   = __expf(mo - m);
        float epm = __expf(p - m);
        den = fmaf(den, c, epm);
        // fp32 accumulation of xl
        float2 f0 = __half22float2(xlh[0]), f1 = __half22float2(xlh[1]);
        float2 f2 = __half22float2(xlh[2]), f3 = __half22float2(xlh[3]);
        float xv[8] = {f0.x, f0.y, f1.x, f1.y, f2.x, f2.y, f3.x, f3.y};
        #pragma unroll
        for (int j = 0; j < 8; j++) acc[j] = fmaf(acc[j], c, epm * xv[j]);

        se0 = se1; se1 = se2; xl0 = xl1;
    }
    float invden = 1.f / den;

    #pragma unroll
    for (int j = 0; j < 8; j++) {
        acc[j] *= invden;
        acc[j] += __shfl_xor_sync(0xffffffffu, acc[j], 8);
        acc[j] += __shfl_xor_sync(0xffffffffu, acc[j], 16);
    }
    int dbase = (lane & 7) * 8;
    float r[8], s1 = 0.f, s2 = 0.f;
    #pragma unroll
    for (int j = 0; j < 8; j++) {
        float val = g_h[n * 64 + dbase + j] + 0.25f * acc[j] + gatb[dbase + j];
        r[j] = val; s1 += val; s2 += val * val;
    }
    #pragma unroll
    for (int off = 1; off < 32; off <<= 1) {
        s1 += __shfl_xor_sync(0xffffffffu, s1, off);
        s2 += __shfl_xor_sync(0xffffffffu, s2, off);
    }
    float mean = s1 * (1.f / 256.f);
    float var  = s2 * (1.f / 256.f) - mean * mean;
    float inv  = rsqrtf(var + LN_EPS);
    if (lane < 8) {
        #pragma unroll
        for (int j = 0; j < 8; j++) {
            int d = dbase + j;
            g_h[n * 64 + d] = (r[j] - mean) * inv * lnw[d] + lnb[d];
        }
    }
}

// ---------------- FFN + residual + LN2 (32-node register tile) ----------------
__global__ void __launch_bounds__(256)
k_ffn(const float* __restrict__ W1, const float* __restrict__ b1,
      const float* __restrict__ W2, const float* __restrict__ b2,
      const float* __restrict__ lnw, const float* __restrict__ lnb) {
    __shared__ float hsh[32 * 64];
    __shared__ float hid[32 * 128];
    int t = threadIdx.x;
    int n0 = blockIdx.x * 32;
    for (int i = t; i < 32 * 64; i += 256) {
        int nn = n0 + (i >> 6);
        hsh[i] = (nn < NN) ? g_h[nn * 64 + (i & 63)] : 0.f;
    }
    __syncthreads();
    {
        int c = t & 15, rg = t >> 4;
        int j0 = c * 8;
        float acc[2][8];
        #pragma unroll
        for (int r = 0; r < 2; r++)
            #pragma unroll
            for (int j = 0; j < 8; j++) acc[r][j] = 0.f;
        #pragma unroll 4
        for (int k = 0; k < 64; k++) {
            float4 w0 = __ldg((const float4*)(W1 + k * 128 + j0));
            float4 w1 = __ldg((const float4*)(W1 + k * 128 + j0 + 4));
            float wv[8] = {w0.x,w0.y,w0.z,w0.w,w1.x,w1.y,w1.z,w1.w};
            #pragma unroll
            for (int r = 0; r < 2; r++) {
                float hv = hsh[(rg * 2 + r) * 64 + k];
                #pragma unroll
                for (int j = 0; j < 8; j++) acc[r][j] = fmaf(hv, wv[j], acc[r][j]);
            }
        }
        #pragma unroll
        for (int r = 0; r < 2; r++)
            #pragma unroll
            for (int j = 0; j < 8; j++)
                hid[(rg * 2 + r) * 128 + j0 + j] = lrelu(acc[r][j] + b1[j0 + j]);
    }
    __syncthreads();
    {
        int c = t & 7, node = t >> 3;
        int j0 = c * 8;
        float acc[8] = {0,0,0,0,0,0,0,0};
        #pragma unroll 4
        for (int k = 0; k < 128; k++) {
            float4 w0 = __ldg((const float4*)(W2 + k * 64 + j0));
            float4 w1 = __ldg((const float4*)(W2 + k * 64 + j0 + 4));
            float hv = hid[node * 128 + k];
            acc[0] = fmaf(hv, w0.x, acc[0]); acc[1] = fmaf(hv, w0.y, acc[1]);
            acc[2] = fmaf(hv, w0.z, acc[2]); acc[3] = fmaf(hv, w0.w, acc[3]);
            acc[4] = fmaf(hv, w1.x, acc[4]); acc[5] = fmaf(hv, w1.y, acc[5]);
            acc[6] = fmaf(hv, w1.z, acc[6]); acc[7] = fmaf(hv, w1.w, acc[7]);
        }
        float r[8], s1 = 0.f, s2 = 0.f;
        #pragma unroll
        for (int j = 0; j < 8; j++) {
            float val = hsh[node * 64 + j0 + j] + acc[j] + b2[j0 + j];
            r[j] = val; s1 += val; s2 += val * val;
        }
        s1 += __shfl_xor_sync(0xffffffffu, s1, 1);
        s2 += __shfl_xor_sync(0xffffffffu, s2, 1);
        s1 += __shfl_xor_sync(0xffffffffu, s1, 2);
        s2 += __shfl_xor_sync(0xffffffffu, s2, 2);
        s1 += __shfl_xor_sync(0xffffffffu, s1, 4);
        s2 += __shfl_xor_sync(0xffffffffu, s2, 4);
        float mean = s1 * (1.f / 64.f);
        float var  = s2 * (1.f / 64.f) - mean * mean;
        float inv  = rsqrtf(var + LN_EPS);
        int n = n0 + node;
        if (n < NN) {
            #pragma unroll
            for (int j = 0; j < 8; j++) {
                int d = j0 + j;
                g_h[n * 64 + d] = (r[j] - mean) * inv * lnw[d] + lnb[d];
            }
        }
    }
}

// ---------------- global context latent + group reduce ----------------
__global__ void __launch_bounds__(256)
k_lat(const float* __restrict__ W1, const float* __restrict__ b1,
      const float* __restrict__ W2, const float* __restrict__ b2,
      const int* __restrict__ batch) {
    __shared__ float hsh[32 * 64];
    __shared__ float hid[32 * 64];
    __shared__ float psum[64];
    __shared__ float pmax[64];
    __shared__ int sgmin, sgmax;
    int t = threadIdx.x;
    int n0 = blockIdx.x * 32;
    for (int i = t; i < 32 * 64; i += 256) {
        int nn = n0 + (i >> 6);
        hsh[i] = (nn < NN) ? g_h[nn * 64 + (i & 63)] : 0.f;
    }
    if (t == 0) {
        sgmin = batch[min(n0, NN - 1)];
        sgmax = batch[min(n0 + 31, NN - 1)];
    }
    __syncthreads();
    int c = t & 7, node = t >> 3;
    int j0 = c * 8;
    {
        float acc[8] = {0,0,0,0,0,0,0,0};
        #pragma unroll 4
        for (int k = 0; k < 64; k++) {
            float4 w0 = __ldg((const float4*)(W1 + k * 64 + j0));
            float4 w1 = __ldg((const float4*)(W1 + k * 64 + j0 + 4));
            float hv = hsh[node * 64 + k];
            acc[0] = fmaf(hv, w0.x, acc[0]); acc[1] = fmaf(hv, w0.y, acc[1]);
            acc[2] = fmaf(hv, w0.z, acc[2]); acc[3] = fmaf(hv, w0.w, acc[3]);
            acc[4] = fmaf(hv, w1.x, acc[4]); acc[5] = fmaf(hv, w1.y, acc[5]);
            acc[6] = fmaf(hv, w1.z, acc[6]); acc[7] = fmaf(hv, w1.w, acc[7]);
        }
        #pragma unroll
        for (int j = 0; j < 8; j++)
            hid[node * 64 + j0 + j] = lrelu(acc[j] + b1[j0 + j]);
    }
    __syncthreads();
    float lat[8];
    {
        float acc[8] = {0,0,0,0,0,0,0,0};
        #pragma unroll 4
        for (int k = 0; k < 64; k++) {
            float4 w0 = __ldg((const float4*)(W2 + k * 64 + j0));
            float4 w1 = __ldg((const float4*)(W2 + k * 64 + j0 + 4));
            float hv = hid[node * 64 + k];
            acc[0] = fmaf(hv, w0.x, acc[0]); acc[1] = fmaf(hv, w0.y, acc[1]);
            acc[2] = fmaf(hv, w0.z, acc[2]); acc[3] = fmaf(hv, w0.w, acc[3]);
            acc[4] = fmaf(hv, w1.x, acc[4]); acc[5] = fmaf(hv, w1.y, acc[5]);
            acc[6] = fmaf(hv, w1.z, acc[6]); acc[7] = fmaf(hv, w1.w, acc[7]);
        }
        #pragma unroll
        for (int j = 0; j < 8; j++) lat[j] = acc[j] + b2[j0 + j];
    }
    int n = n0 + node;
    bool valid = (n < NN);
    int g = valid ? batch[n] : -1;
    for (int gg = sgmin; gg <= sgmax; gg++) {
        if (t < 64) { psum[t] = 0.f; pmax[t] = -3.402823466e38f; }
        __syncthreads();
        if (valid && g == gg) {
            #pragma unroll
            for (int j = 0; j < 8; j++) {
                atomicAdd(&psum[j0 + j], lat[j]);
                atomicMaxFloatS(&pmax[j0 + j], lat[j]);
            }
        }
        __syncthreads();
        if (t < 64) {
            atomicAdd(&g_gmean[gg * 64 + t], psum[t]);
            atomicMaxFloat(&g_gmax[gg * 64 + t], pmax[t]);
        }
        __syncthreads();
    }
}

// gate compute; then reset gmean/gmax for next layer
__global__ void k_gate(const float* __restrict__ W, const float* __restrict__ b) {
    int t = threadIdx.x;            // 1024 = GGR * DD
    int g = t >> 6, j = t & 63;
    float cntf = fmaxf((float)g_cnt[g], 1.f);
    float invc = 1.f / cntf;
    float acc = b[j];
    #pragma unroll 8
    for (int k = 0; k < 64; k++) acc = fmaf(g_gmean[g * 64 + k] * invc, W[k * 64 + j], acc);
    #pragma unroll 8
    for (int k = 0; k < 64; k++) acc = fmaf(g_gmax[g * 64 + k], W[(64 + k) * 64 + j], acc);
    float gate = 1.f / (1.f + __expf(-acc));
    __syncthreads();                 // all reads of gmean/gmax done
    g_gate[t]  = gate;
    g_gmean[t] = 0.f;
    g_gmax[t]  = -3.402823466e38f;
}

// ---------------- decoder (applies last gate on load) ----------------
__global__ void __launch_bounds__(256)
k_dec(const float* __restrict__ W1, const float* __restrict__ b1,
      const float* __restrict__ W2, const float* __restrict__ b2,
      const int* __restrict__ batch, float* __restrict__ out) {
    __shared__ float W1s[4096];
    __shared__ float hrow[8][64];
    int t = threadIdx.x;
    for (int i = t; i < 4096; i += 256) W1s[i] = W1[i];
    __syncthreads();
    int lane = t & 31, w = t >> 5;
    int n = blockIdx.x * 8 + w;
    if (n >= NN) return;
    int bg = batch[n] * 64;
    hrow[w][lane]      = g_h[n * 64 + lane]      * g_gate[bg + lane];
    hrow[w][lane + 32] = g_h[n * 64 + 32 + lane] * g_gate[bg + lane + 32];
    __syncwarp();
    float tv[2];
    #pragma unroll
    for (int i = 0; i < 2; i++) {
        int d = lane + 32 * i;
        float acc = b1[d];
        #pragma unroll
        for (int k = 0; k < 64; k++) acc = fmaf(hrow[w][k], W1s[k * 64 + d], acc);
        tv[i] = lrelu(acc);
    }
    float p0 = tv[0] * __ldg(&W2[lane * 2])     + tv[1] * __ldg(&W2[(lane + 32) * 2]);
    float p1 = tv[0] * __ldg(&W2[lane * 2 + 1]) + tv[1] * __ldg(&W2[(lane + 32) * 2 + 1]);
    #pragma unroll
    for (int off = 16; off; off >>= 1) {
        p0 += __shfl_down_sync(0xffffffffu, p0, off);
        p1 += __shfl_down_sync(0xffffffffu, p1, off);
    }
    if (lane == 0) {
        out[n * 2 + 0] = p0 + b2[0];
        out[n * 2 + 1] = p1 + b2[1];
    }
}

// ---------------- host launcher ----------------
extern "C" void kernel_launch(void* const* d_in, const int* in_sizes, int n_in,
                              void* d_out, int out_size) {
    const float* x    = (const float*)d_in[0];
    const float* ea   = (const float*)d_in[1];
    const int*   ei   = (const int*)  d_in[2];
    const int*   batch= (const int*)  d_in[3];
    const float* encW = (const float*)d_in[4];
    const float* encb = (const float*)d_in[5];
    const float* Wl   = (const float*)d_in[6];
    const float* bl   = (const float*)d_in[7];
    const float* Wr   = (const float*)d_in[8];
    const float* br   = (const float*)d_in[9];
    const float* We   = (const float*)d_in[10];
    const float* attw = (const float*)d_in[11];
    const float* gatb = (const float*)d_in[12];
    const float* ln1w = (const float*)d_in[13];
    const float* ln1b = (const float*)d_in[14];
    const float* ln2w = (const float*)d_in[15];
    const float* ln2b = (const float*)d_in[16];
    const float* fW1  = (const float*)d_in[17];
    const float* fb1  = (const float*)d_in[18];
    const float* fW2  = (const float*)d_in[19];
    const float* fb2  = (const float*)d_in[20];
    const float* nW1  = (const float*)d_in[21];
    const float* nb1  = (const float*)d_in[22];
    const float* nW2  = (const float*)d_in[23];
    const float* nb2  = (const float*)d_in[24];
    const float* gW   = (const float*)d_in[25];
    const float* gb   = (const float*)d_in[26];
    const float* dW1  = (const float*)d_in[27];
    const float* db1  = (const float*)d_in[28];
    const float* dW2  = (const float*)d_in[29];
    const float* db2  = (const float*)d_in[30];
    float* out = (float*)d_out;

    int nwarp_blocks = (NN + 7) / 8;
    int tile_blocks  = (NN + 31) / 32;

    k_zero<<<(NN + 255) / 256, 256>>>();
    k_deg<<<DEG_BLOCKS, 256>>>(ei, ea);
    k_scan1<<<SCAN_BLOCKS, 1024>>>();
    k_scan2<<<1, 128>>>();
    k_scan3<<<SCAN_BLOCKS, 1024>>>();
    k_fill<<<1024, 256>>>(ei, ea, batch);
    k_enc<<<nwarp_blocks, 256>>>(x, encW, encb);

    for (int l = 0; l < LLY; l++) {
        k_xlxr<<<tile_blocks, 256>>>(Wl + l * 64 * 256, bl + l * 256,
                                     Wr + l * 64 * 256, br + l * 256,
                                     batch, l > 0);
        k_gat<<<nwarp_blocks, 256>>>(We + l * 768, attw + l * 256,
                                     gatb + l * 64, ln1w + l * 64, ln1b + l * 64);
        k_ffn<<<tile_blocks, 256>>>(fW1 + l * 64 * 128, fb1 + l * 128,
                                    fW2 + l * 128 * 64, fb2 + l * 64,
                                    ln2w + l * 64, ln2b + l * 64);
        k_lat<<<tile_blocks, 256>>>(nW1 + l * 4096, nb1 + l * 64,
                                    nW2 + l * 4096, nb2 + l * 64, batch);
        k_gate<<<1, 1024>>>(gW + l * 128 * 64, gb + l * 64);
    }
    k_dec<<<nwarp_blocks, 256>>>(dW1, db1, dW2, db2, batch, out);
}

// round 14
// speedup vs baseline: 1.4147x; 1.4147x over previous
#include <cuda_runtime.h>
#include <cuda_fp16.h>
#include <math.h>

#define NN   50000
#define EE   800000
#define GGR  16
#define DD   64
#define LLY  4
#define INF  7
#define ETOT (EE + NN)
#define NEGS 0.2f
#define LN_EPS 1e-5f
#define DEG_BLOCKS 1024
#define SCAN_BLOCKS ((NN + 1023) / 1024)

// ---------------- device scratch ----------------
__device__ __align__(16) float  g_h[NN * DD];
__device__ __align__(16) __half g_xlh[NN * 256];
__device__ __align__(16) __half g_xrh[NN * 256];
__device__ int    g_deg[NN];
__device__ int    g_rowptr[NN + 1];
__device__ int    g_fillptr[NN];
__device__ int    g_bsum[SCAN_BLOCKS];
__device__ int    g_boff[SCAN_BLOCKS];
__device__ __align__(16) float4 g_sea[ETOT];   // {src(asfloat), ea0, ea1, ea2}
__device__ float  g_eapart[DEG_BLOCKS * 3];
__device__ float  g_easum[3];
__device__ int    g_cnt[GGR];
__device__ float  g_gmean[GGR * DD];
__device__ float  g_gmax[GGR * DD];
__device__ float  g_gate[GGR * DD];

__device__ __forceinline__ float lrelu(float x) {
    return fmaxf(x, 0.f) + NEGS * fminf(x, 0.f);
}

__device__ __forceinline__ void atomicMaxFloat(float* addr, float v) {
    if (v >= 0.f) atomicMax((int*)addr, __float_as_int(v));
    else          atomicMin((unsigned int*)addr, __float_as_uint(v));
}
__device__ __forceinline__ void atomicMaxFloatS(float* addr, float v) {
    if (v >= 0.f) atomicMax((int*)addr, __float_as_int(v));
    else          atomicMin((unsigned int*)addr, __float_as_uint(v));
}

// ---------------- setup ----------------
__global__ void k_zero() {
    int i = blockIdx.x * blockDim.x + threadIdx.x;
    if (i < NN)  g_deg[i] = 1;          // self loop pre-counted
    if (i < GGR) g_cnt[i] = 0;
    if (i < GGR * DD) { g_gmean[i] = 0.f; g_gmax[i] = -3.402823466e38f; }
}

__global__ void k_deg(const int* __restrict__ ei, const float* __restrict__ ea) {
    __shared__ float p0s[8], p1s[8], p2s[8];
    float s0 = 0.f, s1 = 0.f, s2 = 0.f;
    int stride = gridDim.x * blockDim.x;
    for (int e = blockIdx.x * blockDim.x + threadIdx.x; e < EE; e += stride) {
        atomicAdd(&g_deg[ei[EE + e]], 1);
        s0 += ea[e * 3 + 0];
        s1 += ea[e * 3 + 1];
        s2 += ea[e * 3 + 2];
    }
    #pragma unroll
    for (int off = 16; off; off >>= 1) {
        s0 += __shfl_down_sync(0xffffffffu, s0, off);
        s1 += __shfl_down_sync(0xffffffffu, s1, off);
        s2 += __shfl_down_sync(0xffffffffu, s2, off);
    }
    int w = threadIdx.x >> 5;
    if ((threadIdx.x & 31) == 0) { p0s[w] = s0; p1s[w] = s1; p2s[w] = s2; }
    __syncthreads();
    if (threadIdx.x == 0) {
        float a = 0.f, b = 0.f, c = 0.f;
        #pragma unroll
        for (int i = 0; i < 8; i++) { a += p0s[i]; b += p1s[i]; c += p2s[i]; }
        g_eapart[blockIdx.x * 3 + 0] = a;
        g_eapart[blockIdx.x * 3 + 1] = b;
        g_eapart[blockIdx.x * 3 + 2] = c;
    }
}

// ---- 3-phase parallel exclusive scan of g_deg ----
__global__ void k_scan1() {            // grid SCAN_BLOCKS, block 1024
    __shared__ int wsum[32];
    int t = threadIdx.x, lane = t & 31, w = t >> 5;
    int i = blockIdx.x * 1024 + t;
    int v = (i < NN) ? g_deg[i] : 0;
    int incl = v;
    #pragma unroll
    for (int off = 1; off < 32; off <<= 1) {
        int u = __shfl_up_sync(0xffffffffu, incl, off);
        if (lane >= off) incl += u;
    }
    if (lane == 31) wsum[w] = incl;
    __syncthreads();
    if (w == 0) {
        int x = wsum[lane];
        int xin = x;
        #pragma unroll
        for (int off = 1; off < 32; off <<= 1) {
            int u = __shfl_up_sync(0xffffffffu, xin, off);
            if (lane >= off) xin += u;
        }
        wsum[lane] = xin - x;
    }
    __syncthreads();
    int excl = wsum[w] + incl - v;
    if (i < NN) g_rowptr[i] = excl;        // block-local exclusive
    if (t == 1023) g_bsum[blockIdx.x] = wsum[31] + incl;
}

__global__ void k_scan2() {            // 1 block, 128 threads
    int t = threadIdx.x, lane = t & 31, w = t >> 5;
    if (w < 3) {
        float s = 0.f;
        for (int i = lane; i < DEG_BLOCKS; i += 32) s += g_eapart[i * 3 + w];
        #pragma unroll
        for (int off = 16; off; off >>= 1)
            s += __shfl_down_sync(0xffffffffu, s, off);
        if (lane == 0) g_easum[w] = s;
    }
    if (w == 3 && lane == 0) {
        int run = 0;
        for (int b = 0; b < SCAN_BLOCKS; b++) { g_boff[b] = run; run += g_bsum[b]; }
        g_rowptr[NN] = run;
    }
}

__global__ void k_scan3() {            // grid SCAN_BLOCKS, block 1024
    int i = blockIdx.x * 1024 + threadIdx.x;
    if (i < NN) {
        int val = g_rowptr[i] + g_boff[blockIdx.x];
        g_rowptr[i]  = val;
        g_fillptr[i] = val;
    }
}

__global__ void k_fill(const int* __restrict__ ei, const float* __restrict__ ea,
                       const int* __restrict__ batch) {
    const float inv_e = 1.f / (float)EE;
    float em0 = g_easum[0] * inv_e, em1 = g_easum[1] * inv_e, em2 = g_easum[2] * inv_e;
    int stride = gridDim.x * blockDim.x;
    for (int e = blockIdx.x * blockDim.x + threadIdx.x; e < ETOT; e += stride) {
        int dst; float4 v;
        if (e < EE) {
            dst = ei[EE + e];
            v = make_float4(__int_as_float(ei[e]), ea[e*3], ea[e*3+1], ea[e*3+2]);
        } else {
            dst = e - EE;
            v = make_float4(__int_as_float(dst), em0, em1, em2);
            atomicAdd(&g_cnt[batch[e - EE]], 1);
        }
        int pos = atomicAdd(&g_fillptr[dst], 1);
        g_sea[pos] = v;
    }
}

// ---------------- encoder ----------------
__global__ void k_enc(const float* __restrict__ x, const float* __restrict__ W,
                      const float* __restrict__ b) {
    __shared__ float Ws[INF * DD];
    __shared__ float bs[DD];
    int t = threadIdx.x;
    for (int i = t; i < INF * DD; i += blockDim.x) Ws[i] = W[i];
    for (int i = t; i < DD; i += blockDim.x) bs[i] = b[i];
    __syncthreads();
    int lane = t & 31, w = t >> 5;
    int n = blockIdx.x * 8 + w;
    if (n >= NN) return;
    float xv[INF];
    #pragma unroll
    for (int k = 0; k < INF; k++) xv[k] = x[n * INF + k];
    #pragma unroll
    for (int i = 0; i < 2; i++) {
        int d = lane + 32 * i;
        float acc = bs[d];
        #pragma unroll
        for (int k = 0; k < INF; k++) acc = fmaf(xv[k], Ws[k * DD + d], acc);
        g_h[n * DD + d] = acc;
    }
}

// ---------------- xl/xr GEMM (fp32 FMA, fp16 store); applies prev-layer gate ----------------
__global__ void __launch_bounds__(256, 2)
k_xlxr(const float* __restrict__ Wl, const float* __restrict__ bl,
       const float* __restrict__ Wr, const float* __restrict__ br,
       const int* __restrict__ batch, int use_gate) {
    __shared__ float hsh[32 * 64];
    int t = threadIdx.x;
    int n0 = blockIdx.x * 32;
    for (int i = t; i < 32 * 64; i += 256) {
        int nn = n0 + (i >> 6);
        int d = i & 63;
        float v = 0.f;
        if (nn < NN) {
            v = g_h[nn * 64 + d];
            if (use_gate) {
                v *= g_gate[batch[nn] * 64 + d];
                g_h[nn * 64 + d] = v;
            }
        }
        hsh[i] = v;
    }
    __syncthreads();
    int cg = t & 63, rg = t >> 6;
    int j0 = cg * 8;
    const float* W  = (j0 < 256) ? Wl : Wr;
    const float* bb = (j0 < 256) ? bl : br;
    __half* out = (j0 < 256) ? g_xlh : g_xrh;
    int jj = (j0 < 256) ? j0 : (j0 - 256);

    float acc[8][8];
    #pragma unroll
    for (int r = 0; r < 8; r++)
        #pragma unroll
        for (int c = 0; c < 8; c++) acc[r][c] = 0.f;

    #pragma unroll 4
    for (int k = 0; k < 64; k++) {
        float4 w0 = *(const float4*)(W + k * 256 + jj);
        float4 w1 = *(const float4*)(W + k * 256 + jj + 4);
        float wv[8] = {w0.x, w0.y, w0.z, w0.w, w1.x, w1.y, w1.z, w1.w};
        #pragma unroll
        for (int r = 0; r < 8; r++) {
            float hv = hsh[(rg * 8 + r) * 64 + k];
            #pragma unroll
            for (int c = 0; c < 8; c++) acc[r][c] = fmaf(hv, wv[c], acc[r][c]);
        }
    }
    float bv[8];
    #pragma unroll
    for (int c = 0; c < 8; c++) bv[c] = bb[jj + c];
    #pragma unroll
    for (int r = 0; r < 8; r++) {
        int n = n0 + rg * 8 + r;
        if (n < NN) {
            __half2 p0 = __floats2half2_rn(acc[r][0]+bv[0], acc[r][1]+bv[1]);
            __half2 p1 = __floats2half2_rn(acc[r][2]+bv[2], acc[r][3]+bv[3]);
            __half2 p2 = __floats2half2_rn(acc[r][4]+bv[4], acc[r][5]+bv[5]);
            __half2 p3 = __floats2half2_rn(acc[r][6]+bv[6], acc[r][7]+bv[7]);
            uint4 u = make_uint4(*(unsigned*)&p0, *(unsigned*)&p1,
                                 *(unsigned*)&p2, *(unsigned*)&p3);
            *(uint4*)(out + (size_t)n * 256 + jj) = u;
        }
    }
}

// ---------------- fused GATv2 (R9 fp32 loop) + residual + LN1 ----------------
__global__ void __launch_bounds__(256)
k_gat(const float* __restrict__ We, const float* __restrict__ attw,
      const float* __restrict__ gatb, const float* __restrict__ lnw,
      const float* __restrict__ lnb) {
    int t = threadIdx.x, lane = t & 31, w = t >> 5;
    int n = blockIdx.x * 8 + w;
    if (n >= NN) return;
    int v0 = lane * 8;

    float we0[8], we1[8], we2[8], av[8];
    #pragma unroll
    for (int j = 0; j < 8; j++) {
        we0[j] = We[v0 + j];
        we1[j] = We[256 + v0 + j];
        we2[j] = We[512 + v0 + j];
        av[j]  = attw[v0 + j];
    }
    float xr8[8];
    {
        uint4 xp = *(const uint4*)(g_xrh + (size_t)n * 256 + v0);
        __half2 h0, h1, h2, h3;
        *(unsigned*)&h0 = xp.x; *(unsigned*)&h1 = xp.y;
        *(unsigned*)&h2 = xp.z; *(unsigned*)&h3 = xp.w;
        float2 f0 = __half22float2(h0), f1 = __half22float2(h1);
        float2 f2 = __half22float2(h2), f3 = __half22float2(h3);
        xr8[0]=f0.x; xr8[1]=f0.y; xr8[2]=f1.x; xr8[3]=f1.y;
        xr8[4]=f2.x; xr8[5]=f2.y; xr8[6]=f3.x; xr8[7]=f3.y;
    }

    int beg = g_rowptr[n], end = g_rowptr[n + 1];

    float m = -INFINITY, den = 0.f;
    float acc[8] = {0.f,0.f,0.f,0.f,0.f,0.f,0.f,0.f};

    float4 se0 = make_float4(0.f,0.f,0.f,0.f), se1 = se0;
    uint4 xl0 = make_uint4(0,0,0,0);
    if (beg < end)     se0 = g_sea[beg];
    if (beg + 1 < end) se1 = g_sea[beg + 1];
    if (beg < end)
        xl0 = *(const uint4*)(g_xlh + (size_t)__float_as_int(se0.x) * 256 + v0);

    for (int k = beg; k < end; k++) {
        uint4 xl1 = xl0;
        if (k + 1 < end)
            xl1 = *(const uint4*)(g_xlh + (size_t)__float_as_int(se1.x) * 256 + v0);
        float4 se2 = (k + 2 < end) ? g_sea[k + 2] : se1;

        __half2 h0, h1, h2, h3;
        *(unsigned*)&h0 = xl0.x; *(unsigned*)&h1 = xl0.y;
        *(unsigned*)&h2 = xl0.z; *(unsigned*)&h3 = xl0.w;
        float2 f0 = __half22float2(h0), f1 = __half22float2(h1);
        float2 f2 = __half22float2(h2), f3 = __half22float2(h3);
        float xv[8] = {f0.x, f0.y, f1.x, f1.y, f2.x, f2.y, f3.x, f3.y};

        float p = 0.f;
        #pragma unroll
        for (int j = 0; j < 8; j++) {
            float sv = xv[j] + xr8[j];
            sv = fmaf(se0.y, we0[j], sv);
            sv = fmaf(se0.z, we1[j], sv);
            sv = fmaf(se0.w, we2[j], sv);
            p = fmaf(av[j], lrelu(sv), p);
        }
        p += __shfl_xor_sync(0xffffffffu, p, 1);
        p += __shfl_xor_sync(0xffffffffu, p, 2);
        p += __shfl_xor_sync(0xffffffffu, p, 4);
        float mo = m;
        m = fmaxf(m, p);
        float c   = __expf(mo - m);
        float epm = __expf(p - m);
        den = fmaf(den, c, epm);
        #pragma unroll
        for (int j = 0; j < 8; j++) acc[j] = fmaf(acc[j], c, epm * xv[j]);

        se0 = se1; se1 = se2; xl0 = xl1;
    }
    float invden = 1.f / den;

    #pragma unroll
    for (int j = 0; j < 8; j++) {
        acc[j] *= invden;
        acc[j] += __shfl_xor_sync(0xffffffffu, acc[j], 8);
        acc[j] += __shfl_xor_sync(0xffffffffu, acc[j], 16);
    }
    int dbase = (lane & 7) * 8;
    float r[8], s1 = 0.f, s2 = 0.f;
    #pragma unroll
    for (int j = 0; j < 8; j++) {
        float val = g_h[n * 64 + dbase + j] + 0.25f * acc[j] + gatb[dbase + j];
        r[j] = val; s1 += val; s2 += val * val;
    }
    #pragma unroll
    for (int off = 1; off < 32; off <<= 1) {
        s1 += __shfl_xor_sync(0xffffffffu, s1, off);
        s2 += __shfl_xor_sync(0xffffffffu, s2, off);
    }
    float mean = s1 * (1.f / 256.f);
    float var  = s2 * (1.f / 256.f) - mean * mean;
    float inv  = rsqrtf(var + LN_EPS);
    if (lane < 8) {
        #pragma unroll
        for (int j = 0; j < 8; j++) {
            int d = dbase + j;
            g_h[n * 64 + d] = (r[j] - mean) * inv * lnw[d] + lnb[d];
        }
    }
}

// ---------------- fused FFN+LN2 then n2g latent + group reduce ----------------
__global__ void __launch_bounds__(256)
k_ffnlat(const float* __restrict__ W1, const float* __restrict__ b1,
         const float* __restrict__ W2, const float* __restrict__ b2,
         const float* __restrict__ lnw, const float* __restrict__ lnb,
         const float* __restrict__ nW1, const float* __restrict__ nb1,
         const float* __restrict__ nW2, const float* __restrict__ nb2,
         const int* __restrict__ batch) {
    __shared__ float hsh[32 * 64];
    __shared__ float hid[32 * 128];
    __shared__ float hidl[32 * 64];
    __shared__ float psum[64];
    __shared__ float pmax[64];
    __shared__ int sgmin, sgmax;
    int t = threadIdx.x;
    int n0 = blockIdx.x * 32;
    for (int i = t; i < 32 * 64; i += 256) {
        int nn = n0 + (i >> 6);
        hsh[i] = (nn < NN) ? g_h[nn * 64 + (i & 63)] : 0.f;
    }
    if (t == 0) {
        sgmin = batch[min(n0, NN - 1)];
        sgmax = batch[min(n0 + 31, NN - 1)];
    }
    __syncthreads();
    // FFN stage 1: hid = lrelu(h @ W1 + b1)
    {
        int c = t & 15, rg = t >> 4;
        int j0 = c * 8;
        float acc[2][8];
        #pragma unroll
        for (int r = 0; r < 2; r++)
            #pragma unroll
            for (int j = 0; j < 8; j++) acc[r][j] = 0.f;
        #pragma unroll 4
        for (int k = 0; k < 64; k++) {
            float4 w0 = __ldg((const float4*)(W1 + k * 128 + j0));
            float4 w1 = __ldg((const float4*)(W1 + k * 128 + j0 + 4));
            float wv[8] = {w0.x,w0.y,w0.z,w0.w,w1.x,w1.y,w1.z,w1.w};
            #pragma unroll
            for (int r = 0; r < 2; r++) {
                float hv = hsh[(rg * 2 + r) * 64 + k];
                #pragma unroll
                for (int j = 0; j < 8; j++) acc[r][j] = fmaf(hv, wv[j], acc[r][j]);
            }
        }
        #pragma unroll
        for (int r = 0; r < 2; r++)
            #pragma unroll
            for (int j = 0; j < 8; j++)
                hid[(rg * 2 + r) * 128 + j0 + j] = lrelu(acc[r][j] + b1[j0 + j]);
    }
    __syncthreads();
    // FFN stage 2 + residual + LN2; write g_h and refresh hsh with normalized h
    int c = t & 7, node = t >> 3;
    int j0 = c * 8;
    {
        float acc[8] = {0,0,0,0,0,0,0,0};
        #pragma unroll 4
        for (int k = 0; k < 128; k++) {
            float4 w0 = __ldg((const float4*)(W2 + k * 64 + j0));
            float4 w1 = __ldg((const float4*)(W2 + k * 64 + j0 + 4));
            float hv = hid[node * 128 + k];
            acc[0] = fmaf(hv, w0.x, acc[0]); acc[1] = fmaf(hv, w0.y, acc[1]);
            acc[2] = fmaf(hv, w0.z, acc[2]); acc[3] = fmaf(hv, w0.w, acc[3]);
            acc[4] = fmaf(hv, w1.x, acc[4]); acc[5] = fmaf(hv, w1.y, acc[5]);
            acc[6] = fmaf(hv, w1.z, acc[6]); acc[7] = fmaf(hv, w1.w, acc[7]);
        }
        float r[8], s1 = 0.f, s2 = 0.f;
        #pragma unroll
        for (int j = 0; j < 8; j++) {
            float val = hsh[node * 64 + j0 + j] + acc[j] + b2[j0 + j];
            r[j] = val; s1 += val; s2 += val * val;
        }
        s1 += __shfl_xor_sync(0xffffffffu, s1, 1);
        s2 += __shfl_xor_sync(0xffffffffu, s2, 1);
        s1 += __shfl_xor_sync(0xffffffffu, s1, 2);
        s2 += __shfl_xor_sync(0xffffffffu, s2, 2);
        s1 += __shfl_xor_sync(0xffffffffu, s1, 4);
        s2 += __shfl_xor_sync(0xffffffffu, s2, 4);
        float mean = s1 * (1.f / 64.f);
        float var  = s2 * (1.f / 64.f) - mean * mean;
        float inv  = rsqrtf(var + LN_EPS);
        int n = n0 + node;
        #pragma unroll
        for (int j = 0; j < 8; j++) {
            int d = j0 + j;
            float val = (r[j] - mean) * inv * lnw[d] + lnb[d];
            hsh[node * 64 + d] = val;
            if (n < NN) g_h[n * 64 + d] = val;
        }
    }
    __syncthreads();
    // n2g stage 1
    {
        float acc[8] = {0,0,0,0,0,0,0,0};
        #pragma unroll 4
        for (int k = 0; k < 64; k++) {
            float4 w0 = __ldg((const float4*)(nW1 + k * 64 + j0));
            float4 w1 = __ldg((const float4*)(nW1 + k * 64 + j0 + 4));
            float hv = hsh[node * 64 + k];
            acc[0] = fmaf(hv, w0.x, acc[0]); acc[1] = fmaf(hv, w0.y, acc[1]);
            acc[2] = fmaf(hv, w0.z, acc[2]); acc[3] = fmaf(hv, w0.w, acc[3]);
            acc[4] = fmaf(hv, w1.x, acc[4]); acc[5] = fmaf(hv, w1.y, acc[5]);
            acc[6] = fmaf(hv, w1.z, acc[6]); acc[7] = fmaf(hv, w1.w, acc[7]);
        }
        #pragma unroll
        for (int j = 0; j < 8; j++)
            hidl[node * 64 + j0 + j] = lrelu(acc[j] + nb1[j0 + j]);
    }
    __syncthreads();
    // n2g stage 2
    float lat[8];
    {
        float acc[8] = {0,0,0,0,0,0,0,0};
        #pragma unroll 4
        for (int k = 0; k < 64; k++) {
            float4 w0 = __ldg((const float4*)(nW2 + k * 64 + j0));
            float4 w1 = __ldg((const float4*)(nW2 + k * 64 + j0 + 4));
            float hv = hidl[node * 64 + k];
            acc[0] = fmaf(hv, w0.x, acc[0]); acc[1] = fmaf(hv, w0.y, acc[1]);
            acc[2] = fmaf(hv, w0.z, acc[2]); acc[3] = fmaf(hv, w0.w, acc[3]);
            acc[4] = fmaf(hv, w1.x, acc[4]); acc[5] = fmaf(hv, w1.y, acc[5]);
            acc[6] = fmaf(hv, w1.z, acc[6]); acc[7] = fmaf(hv, w1.w, acc[7]);
        }
        #pragma unroll
        for (int j = 0; j < 8; j++) lat[j] = acc[j] + nb2[j0 + j];
    }
    int n = n0 + node;
    bool valid = (n < NN);
    int g = valid ? batch[n] : -1;
    for (int gg = sgmin; gg <= sgmax; gg++) {
        if (t < 64) { psum[t] = 0.f; pmax[t] = -3.402823466e38f; }
        __syncthreads();
        if (valid && g == gg) {
            #pragma unroll
            for (int j = 0; j < 8; j++) {
                atomicAdd(&psum[j0 + j], lat[j]);
                atomicMaxFloatS(&pmax[j0 + j], lat[j]);
            }
        }
        __syncthreads();
        if (t < 64) {
            atomicAdd(&g_gmean[gg * 64 + t], psum[t]);
            atomicMaxFloat(&g_gmax[gg * 64 + t], pmax[t]);
        }
        __syncthreads();
    }
}

// gate compute; then reset gmean/gmax for next layer
__global__ void k_gate(const float* __restrict__ W, const float* __restrict__ b) {
    int t = threadIdx.x;            // 1024 = GGR * DD
    int g = t >> 6, j = t & 63;
    float cntf = fmaxf((float)g_cnt[g], 1.f);
    float invc = 1.f / cntf;
    float acc = b[j];
    #pragma unroll 8
    for (int k = 0; k < 64; k++) acc = fmaf(g_gmean[g * 64 + k] * invc, W[k * 64 + j], acc);
    #pragma unroll 8
    for (int k = 0; k < 64; k++) acc = fmaf(g_gmax[g * 64 + k], W[(64 + k) * 64 + j], acc);
    float gate = 1.f / (1.f + __expf(-acc));
    __syncthreads();                 // all reads of gmean/gmax done
    g_gate[t]  = gate;
    g_gmean[t] = 0.f;
    g_gmax[t]  = -3.402823466e38f;
}

// ---------------- decoder (applies last gate on load) ----------------
__global__ void __launch_bounds__(256)
k_dec(const float* __restrict__ W1, const float* __restrict__ b1,
      const float* __restrict__ W2, const float* __restrict__ b2,
      const int* __restrict__ batch, float* __restrict__ out) {
    __shared__ float W1s[4096];
    __shared__ float hrow[8][64];
    int t = threadIdx.x;
    for (int i = t; i < 4096; i += 256) W1s[i] = W1[i];
    __syncthreads();
    int lane = t & 31, w = t >> 5;
    int n = blockIdx.x * 8 + w;
    if (n >= NN) return;
    int bg = batch[n] * 64;
    hrow[w][lane]      = g_h[n * 64 + lane]      * g_gate[bg + lane];
    hrow[w][lane + 32] = g_h[n * 64 + 32 + lane] * g_gate[bg + lane + 32];
    __syncwarp();
    float tv[2];
    #pragma unroll
    for (int i = 0; i < 2; i++) {
        int d = lane + 32 * i;
        float acc = b1[d];
        #pragma unroll
        for (int k = 0; k < 64; k++) acc = fmaf(hrow[w][k], W1s[k * 64 + d], acc);
        tv[i] = lrelu(acc);
    }
    float p0 = tv[0] * __ldg(&W2[lane * 2])     + tv[1] * __ldg(&W2[(lane + 32) * 2]);
    float p1 = tv[0] * __ldg(&W2[lane * 2 + 1]) + tv[1] * __ldg(&W2[(lane + 32) * 2 + 1]);
    #pragma unroll
    for (int off = 16; off; off >>= 1) {
        p0 += __shfl_down_sync(0xffffffffu, p0, off);
        p1 += __shfl_down_sync(0xffffffffu, p1, off);
    }
    if (lane == 0) {
        out[n * 2 + 0] = p0 + b2[0];
        out[n * 2 + 1] = p1 + b2[1];
    }
}

// ---------------- host launcher ----------------
extern "C" void kernel_launch(void* const* d_in, const int* in_sizes, int n_in,
                              void* d_out, int out_size) {
    const float* x    = (const float*)d_in[0];
    const float* ea   = (const float*)d_in[1];
    const int*   ei   = (const int*)  d_in[2];
    const int*   batch= (const int*)  d_in[3];
    const float* encW = (const float*)d_in[4];
    const float* encb = (const float*)d_in[5];
    const float* Wl   = (const float*)d_in[6];
    const float* bl   = (const float*)d_in[7];
    const float* Wr   = (const float*)d_in[8];
    const float* br   = (const float*)d_in[9];
    const float* We   = (const float*)d_in[10];
    const float* attw = (const float*)d_in[11];
    const float* gatb = (const float*)d_in[12];
    const float* ln1w = (const float*)d_in[13];
    const float* ln1b = (const float*)d_in[14];
    const float* ln2w = (const float*)d_in[15];
    const float* ln2b = (const float*)d_in[16];
    const float* fW1  = (const float*)d_in[17];
    const float* fb1  = (const float*)d_in[18];
    const float* fW2  = (const float*)d_in[19];
    const float* fb2  = (const float*)d_in[20];
    const float* nW1  = (const float*)d_in[21];
    const float* nb1  = (const float*)d_in[22];
    const float* nW2  = (const float*)d_in[23];
    const float* nb2  = (const float*)d_in[24];
    const float* gW   = (const float*)d_in[25];
    const float* gb   = (const float*)d_in[26];
    const float* dW1  = (const float*)d_in[27];
    const float* db1  = (const float*)d_in[28];
    const float* dW2  = (const float*)d_in[29];
    const float* db2  = (const float*)d_in[30];
    float* out = (float*)d_out;

    int nwarp_blocks = (NN + 7) / 8;
    int tile_blocks  = (NN + 31) / 32;

    k_zero<<<(NN + 255) / 256, 256>>>();
    k_deg<<<DEG_BLOCKS, 256>>>(ei, ea);
    k_scan1<<<SCAN_BLOCKS, 1024>>>();
    k_scan2<<<1, 128>>>();
    k_scan3<<<SCAN_BLOCKS, 1024>>>();
    k_fill<<<1024, 256>>>(ei, ea, batch);
    k_enc<<<nwarp_blocks, 256>>>(x, encW, encb);

    for (int l = 0; l < LLY; l++) {
        k_xlxr<<<tile_blocks, 256>>>(Wl + l * 64 * 256, bl + l * 256,
                                     Wr + l * 64 * 256, br + l * 256,
                                     batch, l > 0);
        k_gat<<<nwarp_blocks, 256>>>(We + l * 768, attw + l * 256,
                                     gatb + l * 64, ln1w + l * 64, ln1b + l * 64);
        k_ffnlat<<<tile_blocks, 256>>>(fW1 + l * 64 * 128, fb1 + l * 128,
                                       fW2 + l * 128 * 64, fb2 + l * 64,
                                       ln2w + l * 64, ln2b + l * 64,
                                       nW1 + l * 4096, nb1 + l * 64,
                                       nW2 + l * 4096, nb2 + l * 64, batch);
        k_gate<<<1, 1024>>>(gW + l * 128 * 64, gb + l * 64);
    }
    k_dec<<<nwarp_blocks, 256>>>(dW1, db1, dW2, db2, batch, out);
}

// round 17
// speedup vs baseline: 1.4544x; 1.0281x over previous
#include <cuda_runtime.h>
#include <cuda_fp16.h>
#include <math.h>

#define NN   50000
#define EE   800000
#define GGR  16
#define DD   64
#define LLY  4
#define INF  7
#define ETOT (EE + NN)
#define NEGS 0.2f
#define LN_EPS 1e-5f
#define DEG_BLOCKS 1024
#define SCAN_BLOCKS ((NN + 1023) / 1024)

// ---------------- device scratch ----------------
__device__ __align__(16) float  g_h[NN * DD];
__device__ __align__(16) __half g_xlh[NN * 256];
__device__ __align__(16) __half g_xrh[NN * 256];
__device__ int    g_deg[NN];
__device__ int    g_rowptr[NN + 1];
__device__ int    g_fillptr[NN];
__device__ int    g_bsum[SCAN_BLOCKS];
__device__ int    g_boff[SCAN_BLOCKS];
__device__ __align__(16) float4 g_sea[ETOT];   // {src(asfloat), ea0, ea1, ea2}
__device__ float  g_eapart[DEG_BLOCKS * 3];
__device__ float  g_easum[3];
__device__ int    g_cnt[GGR];
__device__ float  g_gmean[GGR * DD];
__device__ float  g_gmax[GGR * DD];
__device__ float  g_gate[GGR * DD];

__device__ __forceinline__ float lrelu(float x) {
    return fmaxf(x, 0.f) + NEGS * fminf(x, 0.f);
}

__device__ __forceinline__ void atomicMaxFloat(float* addr, float v) {
    if (v >= 0.f) atomicMax((int*)addr, __float_as_int(v));
    else          atomicMin((unsigned int*)addr, __float_as_uint(v));
}
__device__ __forceinline__ void atomicMaxFloatS(float* addr, float v) {
    if (v >= 0.f) atomicMax((int*)addr, __float_as_int(v));
    else          atomicMin((unsigned int*)addr, __float_as_uint(v));
}

// ---------------- setup ----------------
__global__ void k_zero() {
    int i = blockIdx.x * blockDim.x + threadIdx.x;
    if (i < NN)  g_deg[i] = 1;          // self loop pre-counted
    if (i < GGR) g_cnt[i] = 0;
    if (i < GGR * DD) { g_gmean[i] = 0.f; g_gmax[i] = -3.402823466e38f; }
}

__global__ void k_deg(const int* __restrict__ ei, const float* __restrict__ ea) {
    __shared__ float p0s[8], p1s[8], p2s[8];
    float s0 = 0.f, s1 = 0.f, s2 = 0.f;
    int stride = gridDim.x * blockDim.x;
    for (int e = blockIdx.x * blockDim.x + threadIdx.x; e < EE; e += stride) {
        atomicAdd(&g_deg[ei[EE + e]], 1);
        s0 += ea[e * 3 + 0];
        s1 += ea[e * 3 + 1];
        s2 += ea[e * 3 + 2];
    }
    #pragma unroll
    for (int off = 16; off; off >>= 1) {
        s0 += __shfl_down_sync(0xffffffffu, s0, off);
        s1 += __shfl_down_sync(0xffffffffu, s1, off);
        s2 += __shfl_down_sync(0xffffffffu, s2, off);
    }
    int w = threadIdx.x >> 5;
    if ((threadIdx.x & 31) == 0) { p0s[w] = s0; p1s[w] = s1; p2s[w] = s2; }
    __syncthreads();
    if (threadIdx.x == 0) {
        float a = 0.f, b = 0.f, c = 0.f;
        #pragma unroll
        for (int i = 0; i < 8; i++) { a += p0s[i]; b += p1s[i]; c += p2s[i]; }
        g_eapart[blockIdx.x * 3 + 0] = a;
        g_eapart[blockIdx.x * 3 + 1] = b;
        g_eapart[blockIdx.x * 3 + 2] = c;
    }
}

// ---- 3-phase parallel exclusive scan of g_deg ----
__global__ void k_scan1() {            // grid SCAN_BLOCKS, block 1024
    __shared__ int wsum[32];
    int t = threadIdx.x, lane = t & 31, w = t >> 5;
    int i = blockIdx.x * 1024 + t;
    int v = (i < NN) ? g_deg[i] : 0;
    int incl = v;
    #pragma unroll
    for (int off = 1; off < 32; off <<= 1) {
        int u = __shfl_up_sync(0xffffffffu, incl, off);
        if (lane >= off) incl += u;
    }
    if (lane == 31) wsum[w] = incl;
    __syncthreads();
    if (w == 0) {
        int x = wsum[lane];
        int xin = x;
        #pragma unroll
        for (int off = 1; off < 32; off <<= 1) {
            int u = __shfl_up_sync(0xffffffffu, xin, off);
            if (lane >= off) xin += u;
        }
        wsum[lane] = xin - x;
    }
    __syncthreads();
    int excl = wsum[w] + incl - v;
    if (i < NN) g_rowptr[i] = excl;        // block-local exclusive
    if (t == 1023) g_bsum[blockIdx.x] = wsum[31] + incl;
}

__global__ void k_scan2() {            // 1 block, 128 threads
    int t = threadIdx.x, lane = t & 31, w = t >> 5;
    if (w < 3) {
        float s = 0.f;
        for (int i = lane; i < DEG_BLOCKS; i += 32) s += g_eapart[i * 3 + w];
        #pragma unroll
        for (int off = 16; off; off >>= 1)
            s += __shfl_down_sync(0xffffffffu, s, off);
        if (lane == 0) g_easum[w] = s;
    }
    if (w == 3 && lane == 0) {
        int run = 0;
        for (int b = 0; b < SCAN_BLOCKS; b++) { g_boff[b] = run; run += g_bsum[b]; }
        g_rowptr[NN] = run;
    }
}

__global__ void k_scan3() {            // grid SCAN_BLOCKS, block 1024
    int i = blockIdx.x * 1024 + threadIdx.x;
    if (i < NN) {
        int val = g_rowptr[i] + g_boff[blockIdx.x];
        g_rowptr[i]  = val;
        g_fillptr[i] = val;
    }
}

__global__ void k_fill(const int* __restrict__ ei, const float* __restrict__ ea,
                       const int* __restrict__ batch) {
    const float inv_e = 1.f / (float)EE;
    float em0 = g_easum[0] * inv_e, em1 = g_easum[1] * inv_e, em2 = g_easum[2] * inv_e;
    int stride = gridDim.x * blockDim.x;
    for (int e = blockIdx.x * blockDim.x + threadIdx.x; e < ETOT; e += stride) {
        int dst; float4 v;
        if (e < EE) {
            dst = ei[EE + e];
            v = make_float4(__int_as_float(ei[e]), ea[e*3], ea[e*3+1], ea[e*3+2]);
        } else {
            dst = e - EE;
            v = make_float4(__int_as_float(dst), em0, em1, em2);
            atomicAdd(&g_cnt[batch[e - EE]], 1);
        }
        int pos = atomicAdd(&g_fillptr[dst], 1);
        g_sea[pos] = v;
    }
}

// ---------------- encoder ----------------
__global__ void k_enc(const float* __restrict__ x, const float* __restrict__ W,
                      const float* __restrict__ b) {
    __shared__ float Ws[INF * DD];
    __shared__ float bs[DD];
    int t = threadIdx.x;
    for (int i = t; i < INF * DD; i += blockDim.x) Ws[i] = W[i];
    for (int i = t; i < DD; i += blockDim.x) bs[i] = b[i];
    __syncthreads();
    int lane = t & 31, w = t >> 5;
    int n = blockIdx.x * 8 + w;
    if (n >= NN) return;
    float xv[INF];
    #pragma unroll
    for (int k = 0; k < INF; k++) xv[k] = x[n * INF + k];
    #pragma unroll
    for (int i = 0; i < 2; i++) {
        int d = lane + 32 * i;
        float acc = bs[d];
        #pragma unroll
        for (int k = 0; k < INF; k++) acc = fmaf(xv[k], Ws[k * DD + d], acc);
        g_h[n * DD + d] = acc;
    }
}

// ---------------- xl/xr GEMM (fp32 FMA, fp16 store); applies prev-layer gate ----------------
__global__ void __launch_bounds__(256, 2)
k_xlxr(const float* __restrict__ Wl, const float* __restrict__ bl,
       const float* __restrict__ Wr, const float* __restrict__ br,
       const int* __restrict__ batch, int use_gate) {
    __shared__ float hsh[32 * 64];
    int t = threadIdx.x;
    int n0 = blockIdx.x * 32;
    for (int i = t; i < 32 * 64; i += 256) {
        int nn = n0 + (i >> 6);
        int d = i & 63;
        float v = 0.f;
        if (nn < NN) {
            v = g_h[nn * 64 + d];
            if (use_gate) {
                v *= g_gate[batch[nn] * 64 + d];
                g_h[nn * 64 + d] = v;
            }
        }
        hsh[i] = v;
    }
    __syncthreads();
    int cg = t & 63, rg = t >> 6;
    int j0 = cg * 8;
    const float* W  = (j0 < 256) ? Wl : Wr;
    const float* bb = (j0 < 256) ? bl : br;
    __half* out = (j0 < 256) ? g_xlh : g_xrh;
    int jj = (j0 < 256) ? j0 : (j0 - 256);

    float acc[8][8];
    #pragma unroll
    for (int r = 0; r < 8; r++)
        #pragma unroll
        for (int c = 0; c < 8; c++) acc[r][c] = 0.f;

    #pragma unroll 4
    for (int k = 0; k < 64; k++) {
        float4 w0 = *(const float4*)(W + k * 256 + jj);
        float4 w1 = *(const float4*)(W + k * 256 + jj + 4);
        float wv[8] = {w0.x, w0.y, w0.z, w0.w, w1.x, w1.y, w1.z, w1.w};
        #pragma unroll
        for (int r = 0; r < 8; r++) {
            float hv = hsh[(rg * 8 + r) * 64 + k];
            #pragma unroll
            for (int c = 0; c < 8; c++) acc[r][c] = fmaf(hv, wv[c], acc[r][c]);
        }
    }
    float bv[8];
    #pragma unroll
    for (int c = 0; c < 8; c++) bv[c] = bb[jj + c];
    #pragma unroll
    for (int r = 0; r < 8; r++) {
        int n = n0 + rg * 8 + r;
        if (n < NN) {
            __half2 p0 = __floats2half2_rn(acc[r][0]+bv[0], acc[r][1]+bv[1]);
            __half2 p1 = __floats2half2_rn(acc[r][2]+bv[2], acc[r][3]+bv[3]);
            __half2 p2 = __floats2half2_rn(acc[r][4]+bv[4], acc[r][5]+bv[5]);
            __half2 p3 = __floats2half2_rn(acc[r][6]+bv[6], acc[r][7]+bv[7]);
            uint4 u = make_uint4(*(unsigned*)&p0, *(unsigned*)&p1,
                                 *(unsigned*)&p2, *(unsigned*)&p3);
            *(uint4*)(out + (size_t)n * 256 + jj) = u;
        }
    }
}

// ---------------- fused GATv2 (R9 fp32 loop) + residual + LN1 ----------------
__global__ void __launch_bounds__(256)
k_gat(const float* __restrict__ We, const float* __restrict__ attw,
      const float* __restrict__ gatb, const float* __restrict__ lnw,
      const float* __restrict__ lnb) {
    int t = threadIdx.x, lane = t & 31, w = t >> 5;
    int n = blockIdx.x * 8 + w;
    if (n >= NN) return;
    int v0 = lane * 8;

    float we0[8], we1[8], we2[8], av[8];
    #pragma unroll
    for (int j = 0; j < 8; j++) {
        we0[j] = We[v0 + j];
        we1[j] = We[256 + v0 + j];
        we2[j] = We[512 + v0 + j];
        av[j]  = attw[v0 + j];
    }
    float xr8[8];
    {
        uint4 xp = *(const uint4*)(g_xrh + (size_t)n * 256 + v0);
        __half2 h0, h1, h2, h3;
        *(unsigned*)&h0 = xp.x; *(unsigned*)&h1 = xp.y;
        *(unsigned*)&h2 = xp.z; *(unsigned*)&h3 = xp.w;
        float2 f0 = __half22float2(h0), f1 = __half22float2(h1);
        float2 f2 = __half22float2(h2), f3 = __half22float2(h3);
        xr8[0]=f0.x; xr8[1]=f0.y; xr8[2]=f1.x; xr8[3]=f1.y;
        xr8[4]=f2.x; xr8[5]=f2.y; xr8[6]=f3.x; xr8[7]=f3.y;
    }

    int beg = g_rowptr[n], end = g_rowptr[n + 1];

    float m = -INFINITY, den = 0.f;
    float acc[8] = {0.f,0.f,0.f,0.f,0.f,0.f,0.f,0.f};

    float4 se0 = make_float4(0.f,0.f,0.f,0.f), se1 = se0;
    uint4 xl0 = make_uint4(0,0,0,0);
    if (beg < end)     se0 = g_sea[beg];
    if (beg + 1 < end) se1 = g_sea[beg + 1];
    if (beg < end)
        xl0 = *(const uint4*)(g_xlh + (size_t)__float_as_int(se0.x) * 256 + v0);

    for (int k = beg; k < end; k++) {
        uint4 xl1 = xl0;
        if (k + 1 < end)
            xl1 = *(const uint4*)(g_xlh + (size_t)__float_as_int(se1.x) * 256 + v0);
        float4 se2 = (k + 2 < end) ? g_sea[k + 2] : se1;

        __half2 h0, h1, h2, h3;
        *(unsigned*)&h0 = xl0.x; *(unsigned*)&h1 = xl0.y;
        *(unsigned*)&h2 = xl0.z; *(unsigned*)&h3 = xl0.w;
        float2 f0 = __half22float2(h0), f1 = __half22float2(h1);
        float2 f2 = __half22float2(h2), f3 = __half22float2(h3);
        float xv[8] = {f0.x, f0.y, f1.x, f1.y, f2.x, f2.y, f3.x, f3.y};

        float p = 0.f;
        #pragma unroll
        for (int j = 0; j < 8; j++) {
            float sv = xv[j] + xr8[j];
            sv = fmaf(se0.y, we0[j], sv);
            sv = fmaf(se0.z, we1[j], sv);
            sv = fmaf(se0.w, we2[j], sv);
            p = fmaf(av[j], lrelu(sv), p);
        }
        p += __shfl_xor_sync(0xffffffffu, p, 1);
        p += __shfl_xor_sync(0xffffffffu, p, 2);
        p += __shfl_xor_sync(0xffffffffu, p, 4);
        float mo = m;
        m = fmaxf(m, p);
        float c   = __expf(mo - m);
        float epm = __expf(p - m);
        den = fmaf(den, c, epm);
        #pragma unroll
        for (int j = 0; j < 8; j++) acc[j] = fmaf(acc[j], c, epm * xv[j]);

        se0 = se1; se1 = se2; xl0 = xl1;
    }
    float invden = 1.f / den;

    #pragma unroll
    for (int j = 0; j < 8; j++) {
        acc[j] *= invden;
        acc[j] += __shfl_xor_sync(0xffffffffu, acc[j], 8);
        acc[j] += __shfl_xor_sync(0xffffffffu, acc[j], 16);
    }
    int dbase = (lane & 7) * 8;
    float r[8], s1 = 0.f, s2 = 0.f;
    #pragma unroll
    for (int j = 0; j < 8; j++) {
        float val = g_h[n * 64 + dbase + j] + 0.25f * acc[j] + gatb[dbase + j];
        r[j] = val; s1 += val; s2 += val * val;
    }
    #pragma unroll
    for (int off = 1; off < 32; off <<= 1) {
        s1 += __shfl_xor_sync(0xffffffffu, s1, off);
        s2 += __shfl_xor_sync(0xffffffffu, s2, off);
    }
    float mean = s1 * (1.f / 256.f);
    float var  = s2 * (1.f / 256.f) - mean * mean;
    float inv  = rsqrtf(var + LN_EPS);
    if (lane < 8) {
        #pragma unroll
        for (int j = 0; j < 8; j++) {
            int d = dbase + j;
            g_h[n * 64 + d] = (r[j] - mean) * inv * lnw[d] + lnb[d];
        }
    }
}

// ---------------- FFN + residual + LN2 (32-node register tile) ----------------
__global__ void __launch_bounds__(256)
k_ffn(const float* __restrict__ W1, const float* __restrict__ b1,
      const float* __restrict__ W2, const float* __restrict__ b2,
      const float* __restrict__ lnw, const float* __restrict__ lnb) {
    __shared__ float hsh[32 * 64];
    __shared__ float hid[32 * 128];
    int t = threadIdx.x;
    int n0 = blockIdx.x * 32;
    for (int i = t; i < 32 * 64; i += 256) {
        int nn = n0 + (i >> 6);
        hsh[i] = (nn < NN) ? g_h[nn * 64 + (i & 63)] : 0.f;
    }
    __syncthreads();
    {
        int c = t & 15, rg = t >> 4;
        int j0 = c * 8;
        float acc[2][8];
        #pragma unroll
        for (int r = 0; r < 2; r++)
            #pragma unroll
            for (int j = 0; j < 8; j++) acc[r][j] = 0.f;
        #pragma unroll 4
        for (int k = 0; k < 64; k++) {
            float4 w0 = __ldg((const float4*)(W1 + k * 128 + j0));
            float4 w1 = __ldg((const float4*)(W1 + k * 128 + j0 + 4));
            float wv[8] = {w0.x,w0.y,w0.z,w0.w,w1.x,w1.y,w1.z,w1.w};
            #pragma unroll
            for (int r = 0; r < 2; r++) {
                float hv = hsh[(rg * 2 + r) * 64 + k];
                #pragma unroll
                for (int j = 0; j < 8; j++) acc[r][j] = fmaf(hv, wv[j], acc[r][j]);
            }
        }
        #pragma unroll
        for (int r = 0; r < 2; r++)
            #pragma unroll
            for (int j = 0; j < 8; j++)
                hid[(rg * 2 + r) * 128 + j0 + j] = lrelu(acc[r][j] + b1[j0 + j]);
    }
    __syncthreads();
    {
        int c = t & 7, node = t >> 3;
        int j0 = c * 8;
        float acc[8] = {0,0,0,0,0,0,0,0};
        #pragma unroll 4
        for (int k = 0; k < 128; k++) {
            float4 w0 = __ldg((const float4*)(W2 + k * 64 + j0));
            float4 w1 = __ldg((const float4*)(W2 + k * 64 + j0 + 4));
            float hv = hid[node * 128 + k];
            acc[0] = fmaf(hv, w0.x, acc[0]); acc[1] = fmaf(hv, w0.y, acc[1]);
            acc[2] = fmaf(hv, w0.z, acc[2]); acc[3] = fmaf(hv, w0.w, acc[3]);
            acc[4] = fmaf(hv, w1.x, acc[4]); acc[5] = fmaf(hv, w1.y, acc[5]);
            acc[6] = fmaf(hv, w1.z, acc[6]); acc[7] = fmaf(hv, w1.w, acc[7]);
        }
        float r[8], s1 = 0.f, s2 = 0.f;
        #pragma unroll
        for (int j = 0; j < 8; j++) {
            float val = hsh[node * 64 + j0 + j] + acc[j] + b2[j0 + j];
            r[j] = val; s1 += val; s2 += val * val;
        }
        s1 += __shfl_xor_sync(0xffffffffu, s1, 1);
        s2 += __shfl_xor_sync(0xffffffffu, s2, 1);
        s1 += __shfl_xor_sync(0xffffffffu, s1, 2);
        s2 += __shfl_xor_sync(0xffffffffu, s2, 2);
        s1 += __shfl_xor_sync(0xffffffffu, s1, 4);
        s2 += __shfl_xor_sync(0xffffffffu, s2, 4);
        float mean = s1 * (1.f / 64.f);
        float var  = s2 * (1.f / 64.f) - mean * mean;
        float inv  = rsqrtf(var + LN_EPS);
        int n = n0 + node;
        if (n < NN) {
            #pragma unroll
            for (int j = 0; j < 8; j++) {
                int d = j0 + j;
                g_h[n * 64 + d] = (r[j] - mean) * inv * lnw[d] + lnb[d];
            }
        }
    }
}

// ---------------- global context latent + group reduce ----------------
__global__ void __launch_bounds__(256)
k_lat(const float* __restrict__ W1, const float* __restrict__ b1,
      const float* __restrict__ W2, const float* __restrict__ b2,
      const int* __restrict__ batch) {
    __shared__ float hsh[32 * 64];
    __shared__ float hid[32 * 64];
    __shared__ float psum[64];
    __shared__ float pmax[64];
    __shared__ int sgmin, sgmax;
    int t = threadIdx.x;
    int n0 = blockIdx.x * 32;
    for (int i = t; i < 32 * 64; i += 256) {
        int nn = n0 + (i >> 6);
        hsh[i] = (nn < NN) ? g_h[nn * 64 + (i & 63)] : 0.f;
    }
    if (t == 0) {
        sgmin = batch[min(n0, NN - 1)];
        sgmax = batch[min(n0 + 31, NN - 1)];
    }
    __syncthreads();
    int c = t & 7, node = t >> 3;
    int j0 = c * 8;
    {
        float acc[8] = {0,0,0,0,0,0,0,0};
        #pragma unroll 4
        for (int k = 0; k < 64; k++) {
            float4 w0 = __ldg((const float4*)(W1 + k * 64 + j0));
            float4 w1 = __ldg((const float4*)(W1 + k * 64 + j0 + 4));
            float hv = hsh[node * 64 + k];
            acc[0] = fmaf(hv, w0.x, acc[0]); acc[1] = fmaf(hv, w0.y, acc[1]);
            acc[2] = fmaf(hv, w0.z, acc[2]); acc[3] = fmaf(hv, w0.w, acc[3]);
            acc[4] = fmaf(hv, w1.x, acc[4]); acc[5] = fmaf(hv, w1.y, acc[5]);
            acc[6] = fmaf(hv, w1.z, acc[6]); acc[7] = fmaf(hv, w1.w, acc[7]);
        }
        #pragma unroll
        for (int j = 0; j < 8; j++)
            hid[node * 64 + j0 + j] = lrelu(acc[j] + b1[j0 + j]);
    }
    __syncthreads();
    float lat[8];
    {
        float acc[8] = {0,0,0,0,0,0,0,0};
        #pragma unroll 4
        for (int k = 0; k < 64; k++) {
            float4 w0 = __ldg((const float4*)(W2 + k * 64 + j0));
            float4 w1 = __ldg((const float4*)(W2 + k * 64 + j0 + 4));
            float hv = hid[node * 64 + k];
            acc[0] = fmaf(hv, w0.x, acc[0]); acc[1] = fmaf(hv, w0.y, acc[1]);
            acc[2] = fmaf(hv, w0.z, acc[2]); acc[3] = fmaf(hv, w0.w, acc[3]);
            acc[4] = fmaf(hv, w1.x, acc[4]); acc[5] = fmaf(hv, w1.y, acc[5]);
            acc[6] = fmaf(hv, w1.z, acc[6]); acc[7] = fmaf(hv, w1.w, acc[7]);
        }
        #pragma unroll
        for (int j = 0; j < 8; j++) lat[j] = acc[j] + b2[j0 + j];
    }
    int n = n0 + node;
    bool valid = (n < NN);
    int g = valid ? batch[n] : -1;
    for (int gg = sgmin; gg <= sgmax; gg++) {
        if (t < 64) { psum[t] = 0.f; pmax[t] = -3.402823466e38f; }
        __syncthreads();
        if (valid && g == gg) {
            #pragma unroll
            for (int j = 0; j < 8; j++) {
                atomicAdd(&psum[j0 + j], lat[j]);
                atomicMaxFloatS(&pmax[j0 + j], lat[j]);
            }
        }
        __syncthreads();
        if (t < 64) {
            atomicAdd(&g_gmean[gg * 64 + t], psum[t]);
            atomicMaxFloat(&g_gmax[gg * 64 + t], pmax[t]);
        }
        __syncthreads();
    }
}

// gate compute; then reset gmean/gmax for next layer
__global__ void k_gate(const float* __restrict__ W, const float* __restrict__ b) {
    int t = threadIdx.x;            // 1024 = GGR * DD
    int g = t >> 6, j = t & 63;
    float cntf = fmaxf((float)g_cnt[g], 1.f);
    float invc = 1.f / cntf;
    float acc = b[j];
    #pragma unroll 8
    for (int k = 0; k < 64; k++) acc = fmaf(g_gmean[g * 64 + k] * invc, W[k * 64 + j], acc);
    #pragma unroll 8
    for (int k = 0; k < 64; k++) acc = fmaf(g_gmax[g * 64 + k], W[(64 + k) * 64 + j], acc);
    float gate = 1.f / (1.f + __expf(-acc));
    __syncthreads();                 // all reads of gmean/gmax done
    g_gate[t]  = gate;
    g_gmean[t] = 0.f;
    g_gmax[t]  = -3.402823466e38f;
}

// ---------------- decoder (applies last gate on load) ----------------
__global__ void __launch_bounds__(256)
k_dec(const float* __restrict__ W1, const float* __restrict__ b1,
      const float* __restrict__ W2, const float* __restrict__ b2,
      const int* __restrict__ batch, float* __restrict__ out) {
    __shared__ float W1s[4096];
    __shared__ float hrow[8][64];
    int t = threadIdx.x;
    for (int i = t; i < 4096; i += 256) W1s[i] = W1[i];
    __syncthreads();
    int lane = t & 31, w = t >> 5;
    int n = blockIdx.x * 8 + w;
    if (n >= NN) return;
    int bg = batch[n] * 64;
    hrow[w][lane]      = g_h[n * 64 + lane]      * g_gate[bg + lane];
    hrow[w][lane + 32] = g_h[n * 64 + 32 + lane] * g_gate[bg + lane + 32];
    __syncwarp();
    float tv[2];
    #pragma unroll
    for (int i = 0; i < 2; i++) {
        int d = lane + 32 * i;
        float acc = b1[d];
        #pragma unroll
        for (int k = 0; k < 64; k++) acc = fmaf(hrow[w][k], W1s[k * 64 + d], acc);
        tv[i] = lrelu(acc);
    }
    float p0 = tv[0] * __ldg(&W2[lane * 2])     + tv[1] * __ldg(&W2[(lane + 32) * 2]);
    float p1 = tv[0] * __ldg(&W2[lane * 2 + 1]) + tv[1] * __ldg(&W2[(lane + 32) * 2 + 1]);
    #pragma unroll
    for (int off = 16; off; off >>= 1) {
        p0 += __shfl_down_sync(0xffffffffu, p0, off);
        p1 += __shfl_down_sync(0xffffffffu, p1, off);
    }
    if (lane == 0) {
        out[n * 2 + 0] = p0 + b2[0];
        out[n * 2 + 1] = p1 + b2[1];
    }
}

// ---------------- host launcher ----------------
extern "C" void kernel_launch(void* const* d_in, const int* in_sizes, int n_in,
                              void* d_out, int out_size) {
    const float* x    = (const float*)d_in[0];
    const float* ea   = (const float*)d_in[1];
    const int*   ei   = (const int*)  d_in[2];
    const int*   batch= (const int*)  d_in[3];
    const float* encW = (const float*)d_in[4];
    const float* encb = (const float*)d_in[5];
    const float* Wl   = (const float*)d_in[6];
    const float* bl   = (const float*)d_in[7];
    const float* Wr   = (const float*)d_in[8];
    const float* br   = (const float*)d_in[9];
    const float* We   = (const float*)d_in[10];
    const float* attw = (const float*)d_in[11];
    const float* gatb = (const float*)d_in[12];
    const float* ln1w = (const float*)d_in[13];
    const float* ln1b = (const float*)d_in[14];
    const float* ln2w = (const float*)d_in[15];
    const float* ln2b = (const float*)d_in[16];
    const float* fW1  = (const float*)d_in[17];
    const float* fb1  = (const float*)d_in[18];
    const float* fW2  = (const float*)d_in[19];
    const float* fb2  = (const float*)d_in[20];
    const float* nW1  = (const float*)d_in[21];
    const float* nb1  = (const float*)d_in[22];
    const float* nW2  = (const float*)d_in[23];
    const float* nb2  = (const float*)d_in[24];
    const float* gW   = (const float*)d_in[25];
    const float* gb   = (const float*)d_in[26];
    const float* dW1  = (const float*)d_in[27];
    const float* db1  = (const float*)d_in[28];
    const float* dW2  = (const float*)d_in[29];
    const float* db2  = (const float*)d_in[30];
    float* out = (float*)d_out;

    int nwarp_blocks = (NN + 7) / 8;
    int tile_blocks  = (NN + 31) / 32;

    k_zero<<<(NN + 255) / 256, 256>>>();
    k_deg<<<DEG_BLOCKS, 256>>>(ei, ea);
    k_scan1<<<SCAN_BLOCKS, 1024>>>();
    k_scan2<<<1, 128>>>();
    k_scan3<<<SCAN_BLOCKS, 1024>>>();
    k_fill<<<1024, 256>>>(ei, ea, batch);
    k_enc<<<nwarp_blocks, 256>>>(x, encW, encb);

    for (int l = 0; l < LLY; l++) {
        k_xlxr<<<tile_blocks, 256>>>(Wl + l * 64 * 256, bl + l * 256,
                                     Wr + l * 64 * 256, br + l * 256,
                                     batch, l > 0);
        k_gat<<<nwarp_blocks, 256>>>(We + l * 768, attw + l * 256,
                                     gatb + l * 64, ln1w + l * 64, ln1b + l * 64);
        k_ffn<<<tile_blocks, 256>>>(fW1 + l * 64 * 128, fb1 + l * 128,
                                    fW2 + l * 128 * 64, fb2 + l * 64,
                                    ln2w + l * 64, ln2b + l * 64);
        k_lat<<<tile_blocks, 256>>>(nW1 + l * 4096, nb1 + l * 64,
                                    nW2 + l * 4096, nb2 + l * 64, batch);
        k_gate<<<1, 1024>>>(gW + l * 128 * 64, gb + l * 64);
    }
    k_dec<<<nwarp_blocks, 256>>>(dW1, db1, dW2, db2, batch, out);
}